// round 6
// baseline (speedup 1.0000x reference)
#include <cuda_runtime.h>

#define FIN 512
#define HID 16
#define CO  7
#define NMAX 200000

// Scratch (no allocations allowed -> __device__ globals)
__device__ float g_deg [NMAX];
__device__ float g_dinv[NMAX];
__device__ float g_g1  [NMAX * HID];   // (x@W1) * dinv[row]
__device__ float g_t1  [NMAX * HID];   // scatter-add accumulator, layer 1
__device__ float g_g2  [NMAX * 8];     // (relu(out1)@W2) * dinv[row], padded to 8
__device__ float g_t2  [NMAX * 8];     // scatter-add accumulator, layer 2

typedef unsigned long long ull;

// ---------- helpers ----------
__device__ __forceinline__ void red4(float* p, float4 v) {
    asm volatile("red.global.add.v4.f32 [%0], {%1,%2,%3,%4};"
                 :: "l"(p), "f"(v.x), "f"(v.y), "f"(v.z), "f"(v.w) : "memory");
}
__device__ __forceinline__ void red1(float* p, float v) {
    asm volatile("red.global.add.f32 [%0], %1;" :: "l"(p), "f"(v) : "memory");
}
__device__ __forceinline__ ull fma2(ull a, ull b, ull c) {
    ull d;
    asm("fma.rn.f32x2 %0, %1, %2, %3;" : "=l"(d) : "l"(a), "l"(b), "l"(c));
    return d;
}
__device__ __forceinline__ ull pack2(float v) {
    ull r;
    asm("mov.b64 %0, {%1, %1};" : "=l"(r) : "f"(v));
    return r;
}
__device__ __forceinline__ float lo32(ull v) {
    return __uint_as_float((unsigned)(v & 0xffffffffull));
}
__device__ __forceinline__ float hi32(ull v) {
    return __uint_as_float((unsigned)(v >> 32));
}

// ---------- kernels ----------
// zero accumulators, deg = 1 (self loop)
__global__ void k_init(int n) {
    int i = blockIdx.x * blockDim.x + threadIdx.x;
    int total = n * HID;
    if (i < total)  g_t1[i] = 0.0f;
    if (i < n * 8)  g_t2[i] = 0.0f;
    if (i < n)      g_deg[i] = 1.0f;
}

__global__ void k_deg(const int* __restrict__ dst, int E) {
    int i = blockIdx.x * blockDim.x + threadIdx.x;
    if (i < E) red1(&g_deg[dst[i]], 1.0f);
}

__global__ void k_dinv(int n) {
    int i = blockIdx.x * blockDim.x + threadIdx.x;
    if (i < n) g_dinv[i] = rsqrtf(g_deg[i]);   // deg >= 1 always
}

// g1[row] = (x[row] @ W1) * dinv[row]
// Block: 128 threads, 512 rows (4 rows/thread, strided by 128).
// x is staged through shared memory in coalesced [512 rows x 16 k] tiles,
// then the FMA loop reads x from smem (conflict-free, pad-17) and W via
// uniform LDS.64 broadcast. Packed f32x2 FMAs, 8 independent acc chains/row.
#define XB    128
#define XR    4
#define XROWS 512
#define KT    16
#define XPAD  17

__global__ void __launch_bounds__(XB) k_xform(const float* __restrict__ x,
                                              const float* __restrict__ W1, int n) {
    extern __shared__ float smem[];
    float* Ws = smem;                    // [512][16]   = 32768 B
    float* Xs = smem + FIN * HID;        // [512][17]   = 34816 B

    int tid = threadIdx.x;
    int rowBase = blockIdx.x * XROWS;

    // load W1 (2048 float4, 16 per thread)
#pragma unroll
    for (int i = 0; i < (FIN * HID / 4) / XB; i++)
        ((float4*)Ws)[i * XB + tid] = __ldg(&((const float4*)W1)[i * XB + tid]);
    const ull* Ws2 = (const ull*)Ws;     // [k][pair 0..7]

    ull acc[XR][8];
#pragma unroll
    for (int q = 0; q < XR; q++)
#pragma unroll
        for (int p = 0; p < 8; p++) acc[q][p] = 0ull;

    for (int kt = 0; kt < FIN; kt += KT) {
        __syncthreads();   // previous tile consumed (and W ready on 1st iter)
        // stage 512 rows x 16 k: 2048 float4, coalesced (8 rows x 64B per warp)
#pragma unroll
        for (int i = 0; i < 16; i++) {
            int e = i * XB + tid;          // 0..2047
            int r = e >> 2;
            int j = e & 3;
            int grow = rowBase + r;
            float4 v = make_float4(0.f, 0.f, 0.f, 0.f);
            if (grow < n)
                v = __ldg((const float4*)(x + (size_t)grow * FIN + kt) + j);
            float* s = &Xs[r * XPAD + j * 4];
            s[0] = v.x; s[1] = v.y; s[2] = v.z; s[3] = v.w;
        }
        __syncthreads();
#pragma unroll
        for (int c = 0; c < KT; c++) {
            int k = kt + c;
            ull w[8];
#pragma unroll
            for (int p = 0; p < 8; p++) w[p] = Ws2[k * 8 + p];  // uniform broadcast
#pragma unroll
            for (int q = 0; q < XR; q++) {
                float xv = Xs[(tid + XB * q) * XPAD + c];       // conflict-free (17 odd)
                ull x2 = pack2(xv);
#pragma unroll
                for (int p = 0; p < 8; p++) acc[q][p] = fma2(x2, w[p], acc[q][p]);
            }
        }
    }

#pragma unroll
    for (int q = 0; q < XR; q++) {
        int row = rowBase + tid + XB * q;
        if (row < n) {
            float d = g_dinv[row];
            float o[16];
#pragma unroll
            for (int p = 0; p < 8; p++) {
                o[2 * p]     = lo32(acc[q][p]) * d;
                o[2 * p + 1] = hi32(acc[q][p]) * d;
            }
            float4* dst4 = (float4*)&g_g1[(size_t)row * HID];
#pragma unroll
            for (int t = 0; t < 4; t++) dst4[t] = *(float4*)&o[4 * t];
        }
    }
}

// scatter-add g1[src] into t1[dst]
__global__ void k_agg1(const int* __restrict__ src, const int* __restrict__ dst, int E) {
    int i = blockIdx.x * blockDim.x + threadIdx.x;
    if (i >= E) return;
    int s = src[i], d = dst[i];
    const float4* gs = (const float4*)&g_g1[(size_t)s * HID];
    float* td = &g_t1[(size_t)d * HID];
    red4(td + 0,  __ldg(gs + 0));
    red4(td + 4,  __ldg(gs + 1));
    red4(td + 8,  __ldg(gs + 2));
    red4(td + 12, __ldg(gs + 3));
}

// out1 = relu(dinv*(t1 + g1) + b1);  g2 = (out1 @ W2) * dinv
__global__ void k_mid(const float* __restrict__ W2, const float* __restrict__ b1, int n) {
    int i = blockIdx.x * blockDim.x + threadIdx.x;
    if (i >= n) return;
    float d = g_dinv[i];
    float h[16];
#pragma unroll
    for (int q = 0; q < 4; q++) {
        float4 tv = *(const float4*)&g_t1[(size_t)i * HID + 4 * q];
        float4 gv = *(const float4*)&g_g1[(size_t)i * HID + 4 * q];
        h[4 * q + 0] = fmaxf(d * (tv.x + gv.x) + __ldg(&b1[4 * q + 0]), 0.0f);
        h[4 * q + 1] = fmaxf(d * (tv.y + gv.y) + __ldg(&b1[4 * q + 1]), 0.0f);
        h[4 * q + 2] = fmaxf(d * (tv.z + gv.z) + __ldg(&b1[4 * q + 2]), 0.0f);
        h[4 * q + 3] = fmaxf(d * (tv.w + gv.w) + __ldg(&b1[4 * q + 3]), 0.0f);
    }
    float o[CO];
#pragma unroll
    for (int j = 0; j < CO; j++) o[j] = 0.0f;
#pragma unroll
    for (int k = 0; k < HID; k++)
#pragma unroll
        for (int j = 0; j < CO; j++)
            o[j] = fmaf(h[k], __ldg(&W2[k * CO + j]), o[j]);
    float out8[8];
#pragma unroll
    for (int j = 0; j < CO; j++) out8[j] = o[j] * d;
    out8[7] = 0.0f;
    float4* dst4 = (float4*)&g_g2[(size_t)i * 8];
    dst4[0] = *(float4*)&out8[0];
    dst4[1] = *(float4*)&out8[4];
}

// scatter-add g2[src] into t2[dst]
__global__ void k_agg2(const int* __restrict__ src, const int* __restrict__ dst, int E) {
    int i = blockIdx.x * blockDim.x + threadIdx.x;
    if (i >= E) return;
    int s = src[i], d = dst[i];
    const float4* gs = (const float4*)&g_g2[(size_t)s * 8];
    float* td = &g_t2[(size_t)d * 8];
    red4(td + 0, __ldg(gs + 0));
    red4(td + 4, __ldg(gs + 1));
}

// out = dinv*(t2 + g2) + b2
__global__ void k_final(const float* __restrict__ b2, float* __restrict__ out, int n) {
    int i = blockIdx.x * blockDim.x + threadIdx.x;
    if (i >= n) return;
    float d = g_dinv[i];
#pragma unroll
    for (int j = 0; j < CO; j++)
        out[(size_t)i * CO + j] =
            d * (g_t2[(size_t)i * 8 + j] + g_g2[(size_t)i * 8 + j]) + __ldg(&b2[j]);
}

// ---------- launch ----------
extern "C" void kernel_launch(void* const* d_in, const int* in_sizes, int n_in,
                              void* d_out, int out_size) {
    const float* x  = (const float*)d_in[0];
    const int*   ei = (const int*)  d_in[1];
    const float* W1 = (const float*)d_in[2];
    const float* b1 = (const float*)d_in[3];
    const float* W2 = (const float*)d_in[4];
    const float* b2 = (const float*)d_in[5];

    int n = in_sizes[0] / FIN;
    int E = in_sizes[1] / 2;
    const int* src = ei;
    const int* dst = ei + E;

    const int TB = 256;
    int gInit  = (n * HID + TB - 1) / TB;
    int gEdge  = (E + TB - 1) / TB;
    int gNode  = (n + TB - 1) / TB;
    int gXform = (n + XROWS - 1) / XROWS;

    static int smem_set = 0;
    int xsmem = (FIN * HID + XROWS * XPAD) * (int)sizeof(float);  // 67584 B
    if (!smem_set) {
        cudaFuncSetAttribute(k_xform, cudaFuncAttributeMaxDynamicSharedMemorySize, xsmem);
        smem_set = 1;
    }

    k_init <<<gInit,  TB>>>(n);
    k_deg  <<<gEdge,  TB>>>(dst, E);
    k_dinv <<<gNode,  TB>>>(n);
    k_xform<<<gXform, XB, xsmem>>>(x, W1, n);
    k_agg1 <<<gEdge,  TB>>>(src, dst, E);
    k_mid  <<<gNode,  TB>>>(W2, b1, n);
    k_agg2 <<<gEdge,  TB>>>(src, dst, E);
    k_final<<<gNode,  TB>>>(b2, (float*)d_out, n);
}

// round 7
// speedup vs baseline: 1.2880x; 1.2880x over previous
#include <cuda_runtime.h>

#define FIN 512
#define HID 16
#define CO  7
#define NMAX 200000

// Scratch (no allocations allowed -> __device__ globals)
__device__ float g_deg [NMAX];
__device__ float g_dinv[NMAX];
__device__ float g_g1  [NMAX * HID];   // (x@W1) * dinv[row]
__device__ float g_t1  [NMAX * HID];   // scatter-add accumulator, layer 1
__device__ float g_g2  [NMAX * 8];     // (relu(out1)@W2) * dinv[row], padded to 8
__device__ float g_t2  [NMAX * 8];     // scatter-add accumulator, layer 2

typedef unsigned long long ull;

// ---------- helpers ----------
__device__ __forceinline__ void red4(float* p, float4 v) {
    asm volatile("red.global.add.v4.f32 [%0], {%1,%2,%3,%4};"
                 :: "l"(p), "f"(v.x), "f"(v.y), "f"(v.z), "f"(v.w) : "memory");
}
__device__ __forceinline__ void red1(float* p, float v) {
    asm volatile("red.global.add.f32 [%0], %1;" :: "l"(p), "f"(v) : "memory");
}
__device__ __forceinline__ ull fma2(ull a, ull b, ull c) {
    ull d;
    asm("fma.rn.f32x2 %0, %1, %2, %3;" : "=l"(d) : "l"(a), "l"(b), "l"(c));
    return d;
}
__device__ __forceinline__ ull pack2(float v) {
    ull r;
    asm("mov.b64 %0, {%1, %1};" : "=l"(r) : "f"(v));
    return r;
}
__device__ __forceinline__ float lo32(ull v) {
    return __uint_as_float((unsigned)(v & 0xffffffffull));
}
__device__ __forceinline__ float hi32(ull v) {
    return __uint_as_float((unsigned)(v >> 32));
}

// ---------- kernels ----------
// zero accumulators, deg = 1 (self loop)
__global__ void k_init(int n) {
    int i = blockIdx.x * blockDim.x + threadIdx.x;
    int total = n * HID;
    if (i < total)  g_t1[i] = 0.0f;
    if (i < n * 8)  g_t2[i] = 0.0f;
    if (i < n)      g_deg[i] = 1.0f;
}

__global__ void k_deg(const int* __restrict__ dst, int E) {
    int i = blockIdx.x * blockDim.x + threadIdx.x;
    if (i < E) red1(&g_deg[dst[i]], 1.0f);
}

__global__ void k_dinv(int n) {
    int i = blockIdx.x * blockDim.x + threadIdx.x;
    if (i < n) g_dinv[i] = rsqrtf(g_deg[i]);   // deg >= 1 always
}

// ---------------------------------------------------------------------------
// g1[row] = (x[row] @ W1) * dinv[row]
// 128 threads, 256 rows/CTA (2 rows/thread, strided by 128).
// cp.async double-buffered staging of x tiles (8B ops, pad-18 rows keep 8B
// alignment and 2-way-max LDS conflicts); tile t+1 streams while tile t
// computes. W read via broadcast LDS.128. Packed f32x2 FMAs.
// ---------------------------------------------------------------------------
#define XB    128
#define XR    2
#define XROWS 256               // XB * XR
#define KT    16
#define XPAD  18
#define NT    (FIN / KT)        // 32 tiles
#define XBUF  (XROWS * XPAD)    // floats per buffer

__global__ void __launch_bounds__(XB) k_xform(const float* __restrict__ x,
                                              const float* __restrict__ W1, int n) {
    extern __shared__ float smem[];
    float* Ws = smem;                    // [512][16] = 32 KB
    float* Xs = smem + FIN * HID;        // 2 x [256][18] = 36 KB

    const int tid = threadIdx.x;
    const int rowBase = blockIdx.x * XROWS;

    // load W1: 2048 float4, 16 per thread (visible after first barrier)
#pragma unroll
    for (int i = 0; i < 16; i++)
        ((float4*)Ws)[i * XB + tid] = __ldg(&((const float4*)W1)[i * XB + tid]);
    const ulonglong2* W128 = (const ulonglong2*)Ws;   // [k][4 pairs-of-pairs]

    unsigned xs_base = (unsigned)__cvta_generic_to_shared(Xs);

    // stage tile t (k range [t*KT, t*KT+16)) into buffer b
    auto stage = [&](int t, int b) {
        int kt = t * KT;
        unsigned base = xs_base + (unsigned)(b * XBUF) * 4u;
#pragma unroll
        for (int i = 0; i < 16; i++) {
            int o = i * XB + tid;          // 0..2047 (8B ops)
            int r = o >> 3;                // row 0..255
            int m = o & 7;                 // pair 0..7
            int grow = rowBase + r;
            const float* src = x + (size_t)grow * FIN + kt + 2 * m;
            unsigned daddr = base + (unsigned)(r * XPAD + 2 * m) * 4u;
            int sz = (grow < n) ? 8 : 0;   // zero-fill OOB rows
            asm volatile("cp.async.ca.shared.global [%0], [%1], 8, %2;"
                         :: "r"(daddr), "l"(src), "r"(sz));
        }
        asm volatile("cp.async.commit_group;");
    };

    ull acc[XR][8];
#pragma unroll
    for (int q = 0; q < XR; q++)
#pragma unroll
        for (int p = 0; p < 8; p++) acc[q][p] = 0ull;

    stage(0, 0);

#pragma unroll 1
    for (int t = 0; t < NT; t++) {
        int b = t & 1;
        if (t + 1 < NT) {
            stage(t + 1, b ^ 1);
            asm volatile("cp.async.wait_group 1;");   // tile t landed
        } else {
            asm volatile("cp.async.wait_group 0;");
        }
        __syncthreads();

        int kt = t * KT;
        const float* Xb = Xs + b * XBUF;
#pragma unroll
        for (int c = 0; c < KT; c++) {
            int k = kt + c;
            ulonglong2 wA = W128[k * 4 + 0];   // pairs 0,1
            ulonglong2 wB = W128[k * 4 + 1];   // pairs 2,3
            ulonglong2 wC = W128[k * 4 + 2];   // pairs 4,5
            ulonglong2 wD = W128[k * 4 + 3];   // pairs 6,7
#pragma unroll
            for (int q = 0; q < XR; q++) {
                float xv = Xb[(tid + XB * q) * XPAD + c];
                ull x2 = pack2(xv);
                acc[q][0] = fma2(x2, wA.x, acc[q][0]);
                acc[q][1] = fma2(x2, wA.y, acc[q][1]);
                acc[q][2] = fma2(x2, wB.x, acc[q][2]);
                acc[q][3] = fma2(x2, wB.y, acc[q][3]);
                acc[q][4] = fma2(x2, wC.x, acc[q][4]);
                acc[q][5] = fma2(x2, wC.y, acc[q][5]);
                acc[q][6] = fma2(x2, wD.x, acc[q][6]);
                acc[q][7] = fma2(x2, wD.y, acc[q][7]);
            }
        }
        __syncthreads();   // buffer b reused by stage(t+2) next iteration
    }

#pragma unroll
    for (int q = 0; q < XR; q++) {
        int row = rowBase + tid + XB * q;
        if (row < n) {
            float d = g_dinv[row];
            float o[16];
#pragma unroll
            for (int p = 0; p < 8; p++) {
                o[2 * p]     = lo32(acc[q][p]) * d;
                o[2 * p + 1] = hi32(acc[q][p]) * d;
            }
            float4* dst4 = (float4*)&g_g1[(size_t)row * HID];
#pragma unroll
            for (int v = 0; v < 4; v++) dst4[v] = *(float4*)&o[4 * v];
        }
    }
}

// scatter-add g1[src] into t1[dst] — 4 threads per edge (16B each).
// A warp's gather touches 8 rows (8 lines) instead of 32: 4x fewer L1tex
// wavefronts than thread-per-edge, same bytes.
__global__ void k_agg1(const int* __restrict__ src, const int* __restrict__ dst, int E) {
    int i = blockIdx.x * blockDim.x + threadIdx.x;
    int e = i >> 2;
    if (e >= E) return;
    int j = i & 3;
    int s = src[e], d = dst[e];
    float4 v = __ldg((const float4*)&g_g1[(size_t)s * HID] + j);
    red4((float*)((float4*)&g_t1[(size_t)d * HID] + j), v);
}

// out1 = relu(dinv*(t1 + g1) + b1);  g2 = (out1 @ W2) * dinv
__global__ void k_mid(const float* __restrict__ W2, const float* __restrict__ b1, int n) {
    int i = blockIdx.x * blockDim.x + threadIdx.x;
    if (i >= n) return;
    float d = g_dinv[i];
    float h[16];
#pragma unroll
    for (int q = 0; q < 4; q++) {
        float4 tv = *(const float4*)&g_t1[(size_t)i * HID + 4 * q];
        float4 gv = *(const float4*)&g_g1[(size_t)i * HID + 4 * q];
        h[4 * q + 0] = fmaxf(d * (tv.x + gv.x) + __ldg(&b1[4 * q + 0]), 0.0f);
        h[4 * q + 1] = fmaxf(d * (tv.y + gv.y) + __ldg(&b1[4 * q + 1]), 0.0f);
        h[4 * q + 2] = fmaxf(d * (tv.z + gv.z) + __ldg(&b1[4 * q + 2]), 0.0f);
        h[4 * q + 3] = fmaxf(d * (tv.w + gv.w) + __ldg(&b1[4 * q + 3]), 0.0f);
    }
    float o[CO];
#pragma unroll
    for (int j = 0; j < CO; j++) o[j] = 0.0f;
#pragma unroll
    for (int k = 0; k < HID; k++)
#pragma unroll
        for (int j = 0; j < CO; j++)
            o[j] = fmaf(h[k], __ldg(&W2[k * CO + j]), o[j]);
    float out8[8];
#pragma unroll
    for (int j = 0; j < CO; j++) out8[j] = o[j] * d;
    out8[7] = 0.0f;
    float4* dst4 = (float4*)&g_g2[(size_t)i * 8];
    dst4[0] = *(float4*)&out8[0];
    dst4[1] = *(float4*)&out8[4];
}

// scatter-add g2[src] into t2[dst] — 2 threads per edge (16B each).
__global__ void k_agg2(const int* __restrict__ src, const int* __restrict__ dst, int E) {
    int i = blockIdx.x * blockDim.x + threadIdx.x;
    int e = i >> 1;
    if (e >= E) return;
    int j = i & 1;
    int s = src[e], d = dst[e];
    float4 v = __ldg((const float4*)&g_g2[(size_t)s * 8] + j);
    red4((float*)((float4*)&g_t2[(size_t)d * 8] + j), v);
}

// out = dinv*(t2 + g2) + b2
__global__ void k_final(const float* __restrict__ b2, float* __restrict__ out, int n) {
    int i = blockIdx.x * blockDim.x + threadIdx.x;
    if (i >= n) return;
    float d = g_dinv[i];
#pragma unroll
    for (int j = 0; j < CO; j++)
        out[(size_t)i * CO + j] =
            d * (g_t2[(size_t)i * 8 + j] + g_g2[(size_t)i * 8 + j]) + __ldg(&b2[j]);
}

// ---------- launch ----------
extern "C" void kernel_launch(void* const* d_in, const int* in_sizes, int n_in,
                              void* d_out, int out_size) {
    const float* x  = (const float*)d_in[0];
    const int*   ei = (const int*)  d_in[1];
    const float* W1 = (const float*)d_in[2];
    const float* b1 = (const float*)d_in[3];
    const float* W2 = (const float*)d_in[4];
    const float* b2 = (const float*)d_in[5];

    int n = in_sizes[0] / FIN;
    int E = in_sizes[1] / 2;
    const int* src = ei;
    const int* dst = ei + E;

    const int TB = 256;
    int gInit  = (n * HID + TB - 1) / TB;
    int gEdge  = (E + TB - 1) / TB;
    int gEdge4 = (4 * E + TB - 1) / TB;
    int gEdge2 = (2 * E + TB - 1) / TB;
    int gNode  = (n + TB - 1) / TB;
    int gXform = (n + XROWS - 1) / XROWS;

    static int smem_set = 0;
    int xsmem = (FIN * HID + 2 * XBUF) * (int)sizeof(float);  // 69632 B
    if (!smem_set) {
        cudaFuncSetAttribute(k_xform, cudaFuncAttributeMaxDynamicSharedMemorySize, xsmem);
        smem_set = 1;
    }

    k_init <<<gInit,  TB>>>(n);
    k_deg  <<<gEdge,  TB>>>(dst, E);
    k_dinv <<<gNode,  TB>>>(n);
    k_xform<<<gXform, XB, xsmem>>>(x, W1, n);
    k_agg1 <<<gEdge4, TB>>>(src, dst, E);
    k_mid  <<<gNode,  TB>>>(W2, b1, n);
    k_agg2 <<<gEdge2, TB>>>(src, dst, E);
    k_final<<<gNode,  TB>>>(b2, (float*)d_out, n);
}